// round 2
// baseline (speedup 1.0000x reference)
#include <cuda_runtime.h>
#include <math.h>

#define D     256
#define NBANK 512
#define TM    64        // queries per block
#define TN    128       // n-chunk (gemm1) / d-chunk (gemm2)
#define TK    32        // k-chunk
#define SLD   520       // sim row stride (floats), padded
#define BLD   132       // B-tile row stride (floats), padded, %4==0
#define ALD   36        // A-tile row stride (floats), padded, %4==0

// SMEM layout (floats): S[TM*SLD] | At[TM*ALD] | Bt[TK*BLD] | rinv[TM] | rsum[TM]
#define SMEM_FLOATS (TM*SLD + TM*ALD + TK*BLD + TM + TM)
#define SMEM_BYTES  (SMEM_FLOATS * 4)

// Normalized bank scratch (allowed: __device__ global, no allocation)
__device__ float g_embn[NBANK * D];

__global__ void norm_emb_kernel(const float* __restrict__ emb) {
    int n = blockIdx.x;            // 512 blocks
    int t = threadIdx.x;           // 256 threads = D
    float e = emb[n * D + t];
    __shared__ float red[8];
    float s = e * e;
    #pragma unroll
    for (int o = 16; o > 0; o >>= 1) s += __shfl_xor_sync(0xffffffffu, s, o);
    if ((t & 31) == 0) red[t >> 5] = s;
    __syncthreads();
    if (t < 8) {
        float v = red[t];
        #pragma unroll
        for (int o = 4; o > 0; o >>= 1) v += __shfl_xor_sync(0x000000ffu, v, o);
        if (t == 0) red[0] = v;
    }
    __syncthreads();
    float inv = 1.0f / fmaxf(sqrtf(red[0]), 1e-12f);
    g_embn[n * D + t] = e * inv;
}

__global__ __launch_bounds__(256, 1)
void concept_kernel(const float* __restrict__ q,
                    const float* __restrict__ emb,
                    float* __restrict__ vec_out,
                    float* __restrict__ p_out) {
    extern __shared__ float sm[];
    float* S    = sm;                       // TM x SLD : sims -> exp(sims)
    float* At   = S  + TM * SLD;            // TM x ALD : q tile [m][k]
    float* Bt   = At + TM * ALD;            // TK x BLD : bank tile [k][n] / emb tile [k][d]
    float* rinv = Bt + TK * BLD;            // TM : 1/||q||
    float* rsum = rinv + TM;                // TM : 1/sum(exp)

    const int tid  = threadIdx.x;
    const int warp = tid >> 5, lane = tid & 31;
    const int tm   = tid >> 4, tn = tid & 15;       // 16 x 16 thread grid
    const size_t b0 = (size_t)blockIdx.x * TM;

    // ---- 1. per-query inverse L2 norm (coalesced, 8 rows per warp) ----
    #pragma unroll
    for (int mi = 0; mi < 8; mi++) {
        int m = warp * 8 + mi;
        const float* qr = q + (b0 + m) * D;
        float s = 0.f;
        #pragma unroll
        for (int i = 0; i < D / 32; i++) {
            float v = qr[lane + 32 * i];
            s += v * v;
        }
        #pragma unroll
        for (int o = 16; o > 0; o >>= 1) s += __shfl_xor_sync(0xffffffffu, s, o);
        if (lane == 0) rinv[m] = 1.0f / fmaxf(sqrtf(s), 1e-12f);
    }
    __syncthreads();

    // ---- 2. GEMM1: S = (Q/||q||) @ embn^T   (64 x 512) ----
    #pragma unroll 1
    for (int nc = 0; nc < NBANK / TN; nc++) {       // 4 n-chunks
        float acc[4][8];
        #pragma unroll
        for (int i = 0; i < 4; i++)
            #pragma unroll
            for (int j = 0; j < 8; j++) acc[i][j] = 0.f;

        #pragma unroll 1
        for (int kc = 0; kc < D / TK; kc++) {       // 8 k-chunks
            __syncthreads();
            // load A tile: 64x32 of q, row-major [m][k]
            #pragma unroll
            for (int r = 0; r < 2; r++) {
                int f = tid + r * 256;              // 512 float4 total
                int m = f >> 3, kq = (f & 7) << 2;
                float4 v = *(const float4*)(q + (b0 + m) * D + kc * TK + kq);
                *(float4*)(At + m * ALD + kq) = v;
            }
            // load B tile transposed: embn rows [nc*128..), cols [kc*32..) -> Bt[k][n]
            #pragma unroll
            for (int r = 0; r < 4; r++) {
                int f = tid + r * 256;              // 1024 float4 total
                int n = f >> 3, kq = (f & 7) << 2;
                float4 v = *(const float4*)(g_embn + (size_t)(nc * TN + n) * D + kc * TK + kq);
                Bt[(kq + 0) * BLD + n] = v.x;
                Bt[(kq + 1) * BLD + n] = v.y;
                Bt[(kq + 2) * BLD + n] = v.z;
                Bt[(kq + 3) * BLD + n] = v.w;
            }
            __syncthreads();
            #pragma unroll
            for (int kk = 0; kk < TK; kk++) {
                float a[4];
                #pragma unroll
                for (int i = 0; i < 4; i++) a[i] = At[(tm * 4 + i) * ALD + kk];
                float4 bv0 = *(const float4*)(Bt + kk * BLD + tn * 8);
                float4 bv1 = *(const float4*)(Bt + kk * BLD + tn * 8 + 4);
                float b[8] = {bv0.x, bv0.y, bv0.z, bv0.w, bv1.x, bv1.y, bv1.z, bv1.w};
                #pragma unroll
                for (int i = 0; i < 4; i++)
                    #pragma unroll
                    for (int j = 0; j < 8; j++) acc[i][j] = fmaf(a[i], b[j], acc[i][j]);
            }
        }
        // write scaled sims to S
        #pragma unroll
        for (int i = 0; i < 4; i++) {
            int m = tm * 4 + i;
            float sc = rinv[m];
            float* row = S + m * SLD + nc * TN + tn * 8;
            float4 o0 = make_float4(acc[i][0]*sc, acc[i][1]*sc, acc[i][2]*sc, acc[i][3]*sc);
            float4 o1 = make_float4(acc[i][4]*sc, acc[i][5]*sc, acc[i][6]*sc, acc[i][7]*sc);
            *(float4*)(row)     = o0;
            *(float4*)(row + 4) = o1;
        }
    }
    __syncthreads();

    // ---- 3. softmax over N (sims in [-1,1] -> no max subtraction needed) ----
    #pragma unroll 1
    for (int mi = 0; mi < 8; mi++) {
        int m = warp * 8 + mi;
        float* row = S + m * SLD;
        float e[16];
        float ssum = 0.f;
        #pragma unroll
        for (int i = 0; i < 16; i++) {
            float v = __expf(row[lane + 32 * i]);
            e[i] = v;
            ssum += v;
        }
        #pragma unroll
        for (int o = 16; o > 0; o >>= 1) ssum += __shfl_xor_sync(0xffffffffu, ssum, o);
        float inv = 1.0f / ssum;
        float* prow = p_out + (b0 + m) * NBANK;
        #pragma unroll
        for (int i = 0; i < 16; i++) {
            row[lane + 32 * i]  = e[i];          // keep exp values for GEMM2
            prow[lane + 32 * i] = e[i] * inv;    // coalesced p output
        }
        if (lane == 0) rsum[m] = inv;
    }
    __syncthreads();

    // ---- 4. GEMM2: vec = (exp(S) @ emb) * (1/sum)   (64 x 256) ----
    #pragma unroll 1
    for (int dc = 0; dc < D / TN; dc++) {           // 2 d-chunks
        float acc[4][8];
        #pragma unroll
        for (int i = 0; i < 4; i++)
            #pragma unroll
            for (int j = 0; j < 8; j++) acc[i][j] = 0.f;

        #pragma unroll 1
        for (int kc = 0; kc < NBANK / TK; kc++) {   // 16 k-chunks
            __syncthreads();
            // load B tile: emb rows [kc*32..), cols [dc*128..), natural layout [k][d]
            #pragma unroll
            for (int r = 0; r < 4; r++) {
                int f = tid + r * 256;              // 1024 float4
                int k = f >> 5, dq = (f & 31) << 2;
                float4 v = *(const float4*)(emb + (size_t)(kc * TK + k) * D + dc * TN + dq);
                *(float4*)(Bt + k * BLD + dq) = v;
            }
            __syncthreads();
            #pragma unroll
            for (int kk = 0; kk < TK; kk++) {
                float a[4];
                #pragma unroll
                for (int i = 0; i < 4; i++) a[i] = S[(tm * 4 + i) * SLD + kc * TK + kk];
                float4 bv0 = *(const float4*)(Bt + kk * BLD + tn * 8);
                float4 bv1 = *(const float4*)(Bt + kk * BLD + tn * 8 + 4);
                float b[8] = {bv0.x, bv0.y, bv0.z, bv0.w, bv1.x, bv1.y, bv1.z, bv1.w};
                #pragma unroll
                for (int i = 0; i < 4; i++)
                    #pragma unroll
                    for (int j = 0; j < 8; j++) acc[i][j] = fmaf(a[i], b[j], acc[i][j]);
            }
        }
        // write vec (coalesced float4)
        #pragma unroll
        for (int i = 0; i < 4; i++) {
            int m = tm * 4 + i;
            float sc = rsum[m];
            float* vrow = vec_out + (b0 + m) * D + dc * TN + tn * 8;
            float4 o0 = make_float4(acc[i][0]*sc, acc[i][1]*sc, acc[i][2]*sc, acc[i][3]*sc);
            float4 o1 = make_float4(acc[i][4]*sc, acc[i][5]*sc, acc[i][6]*sc, acc[i][7]*sc);
            *(float4*)(vrow)     = o0;
            *(float4*)(vrow + 4) = o1;
        }
    }
}

extern "C" void kernel_launch(void* const* d_in, const int* in_sizes, int n_in,
                              void* d_out, int out_size) {
    const float* q   = (const float*)d_in[0];   // (B, 256)
    const float* emb = (const float*)d_in[1];   // (512, 256)
    const int B = in_sizes[0] / D;

    float* vec_out = (float*)d_out;                         // (B, 256)
    float* p_out   = (float*)d_out + (size_t)B * D;         // (B, 512)

    cudaFuncSetAttribute(concept_kernel,
                         cudaFuncAttributeMaxDynamicSharedMemorySize, SMEM_BYTES);

    norm_emb_kernel<<<NBANK, D>>>(emb);
    concept_kernel<<<B / TM, 256, SMEM_BYTES>>>(q, emb, vec_out, p_out);
}

// round 4
// speedup vs baseline: 1.7037x; 1.7037x over previous
#include <cuda_runtime.h>
#include <cuda_fp16.h>
#include <cstdint>
#include <math.h>

#define D       256
#define NBANK   512
#define TMR     64          // rows (queries) per CTA
#define THREADS 128

// ---------------- device scratch (no allocation allowed) ----------------
__device__ __half g_embn_h[NBANK * D];   // l2-normalized bank fp16, [n][d] (K-major for GEMM1 B)
__device__ __half g_embT_h[D * NBANK];   // raw bank transposed fp16, [d][n] (K-major for GEMM2 B)

// ---------------- SMEM layout ----------------
// strides in halves (row pad +8 halves = +16B keeps ldmatrix conflict-free: stride mod 128B = 16)
#define QH_LDH 264
#define B1_LDH 264
#define EH_LDH 520
#define B2_LDH 520

#define OFF_EH   0
#define SZ_EH    (TMR * EH_LDH * 2)           // 66560
#define OFF_R1   SZ_EH
#define OFF_QH   OFF_R1                        // phase 1
#define SZ_QH    (TMR * QH_LDH * 2)           // 33792
#define OFF_B1A  (OFF_R1 + SZ_QH)
#define OFF_B1B  (OFF_B1A + TMR * B1_LDH * 2)
#define OFF_B2A  OFF_R1                        // phase 2 (reuses QH/B1 space)
#define OFF_B2B  (OFF_R1 + TMR * B2_LDH * 2)
#define OFF_RINV (OFF_R1 + 2 * TMR * B2_LDH * 2)   // 199680
#define OFF_PSUM (OFF_RINV + 256)
#define SMEM_TOTAL (OFF_PSUM + 256)                // 200192 bytes

// ---------------- asm helpers (all sm_80-era, no 'a'-suffix features) ----------------
__device__ __forceinline__ uint32_t smem_u32(const void* p) {
    uint32_t a;
    asm("{ .reg .u64 t; cvta.to.shared.u64 t, %1; cvt.u32.u64 %0, t; }" : "=r"(a) : "l"(p));
    return a;
}
__device__ __forceinline__ void ldsm4(uint32_t* r, uint32_t a) {
    asm volatile("ldmatrix.sync.aligned.m8n8.x4.shared.b16 {%0,%1,%2,%3}, [%4];"
        : "=r"(r[0]), "=r"(r[1]), "=r"(r[2]), "=r"(r[3]) : "r"(a));
}
__device__ __forceinline__ void mma16816(float* c, const uint32_t* a, uint32_t b0, uint32_t b1) {
    asm volatile("mma.sync.aligned.m16n8k16.row.col.f32.f16.f16.f32 "
        "{%0,%1,%2,%3}, {%4,%5,%6,%7}, {%8,%9}, {%0,%1,%2,%3};"
        : "+f"(c[0]), "+f"(c[1]), "+f"(c[2]), "+f"(c[3])
        : "r"(a[0]), "r"(a[1]), "r"(a[2]), "r"(a[3]), "r"(b0), "r"(b1));
}
__device__ __forceinline__ void cpa16(uint32_t s, const void* g) {
    asm volatile("cp.async.cg.shared.global [%0], [%1], 16;" :: "r"(s), "l"(g));
}
__device__ __forceinline__ void cpa_commit() { asm volatile("cp.async.commit_group;" ::: "memory"); }
__device__ __forceinline__ void cpa_wait1()  { asm volatile("cp.async.wait_group 1;" ::: "memory"); }
__device__ __forceinline__ void cpa_wait0()  { asm volatile("cp.async.wait_group 0;" ::: "memory"); }

// exp(x), x in [-1.05, 1.05], FMA-only (avoids the chip-wide MUFU floor)
__device__ __forceinline__ float fast_exp(float x) {
    float t = x * 1.4426950408889634f;
    float r = t + 12582912.0f;
    int   i = __float_as_int(r) - 0x4B400000;
    float f = t - (r - 12582912.0f);
    float p = 1.5403530393381608e-4f;
    p = fmaf(p, f, 1.3333558146428443e-3f);
    p = fmaf(p, f, 9.6181291076284770e-3f);
    p = fmaf(p, f, 5.5504108664821580e-2f);
    p = fmaf(p, f, 2.4022650695910071e-1f);
    p = fmaf(p, f, 6.9314718055994531e-1f);
    p = fmaf(p, f, 1.0f);
    return __int_as_float(__float_as_int(p) + (i << 23));
}

// ---------------- prologue kernels ----------------
__global__ void norm_emb_kernel(const float* __restrict__ emb) {
    int n = blockIdx.x, t = threadIdx.x;
    float e = emb[n * D + t];
    __shared__ float red[8];
    float s = e * e;
    #pragma unroll
    for (int o = 16; o > 0; o >>= 1) s += __shfl_xor_sync(0xffffffffu, s, o);
    if ((t & 31) == 0) red[t >> 5] = s;
    __syncthreads();
    if (t < 8) {
        float v = red[t];
        #pragma unroll
        for (int o = 4; o > 0; o >>= 1) v += __shfl_xor_sync(0x000000ffu, v, o);
        if (t == 0) red[0] = v;
    }
    __syncthreads();
    float inv = 1.0f / fmaxf(sqrtf(red[0]), 1e-12f);
    g_embn_h[n * D + t] = __float2half(e * inv);
}

__global__ void transpose_emb_kernel(const float* __restrict__ emb) {
    __shared__ float tile[32][33];
    int n0 = blockIdx.x * 32, d0 = blockIdx.y * 32;
    int tx = threadIdx.x, ty = threadIdx.y;
    #pragma unroll
    for (int j = ty; j < 32; j += 8) tile[j][tx] = emb[(n0 + j) * D + d0 + tx];
    __syncthreads();
    #pragma unroll
    for (int j = ty; j < 32; j += 8)
        g_embT_h[(size_t)(d0 + j) * NBANK + n0 + tx] = __float2half(tile[tx][j]);
}

// ---------------- chunk loaders (cp.async, one commit group each) ----------------
__device__ __forceinline__ void load_b1_chunk(uint32_t sb, int bufoff, int nc, int tid) {
    const __half* gp = g_embn_h + (size_t)nc * 64 * D;
    #pragma unroll
    for (int i = 0; i < 16; i++) {
        int idx = i * 128 + tid;
        int row = idx >> 5, seg = idx & 31;          // 64 rows x 32 16B-segs
        cpa16(sb + bufoff + row * (B1_LDH * 2) + seg * 16, gp + row * D + seg * 8);
    }
    cpa_commit();
}
__device__ __forceinline__ void load_b2_chunk(uint32_t sb, int bufoff, int dc, int tid) {
    const __half* gp = g_embT_h + (size_t)dc * 64 * NBANK;
    #pragma unroll
    for (int i = 0; i < 32; i++) {
        int idx = i * 128 + tid;
        int row = idx >> 6, seg = idx & 63;          // 64 rows x 64 16B-segs
        cpa16(sb + bufoff + row * (B2_LDH * 2) + seg * 16, gp + row * NBANK + seg * 8);
    }
    cpa_commit();
}

// ---------------- main fused kernel ----------------
__global__ __launch_bounds__(THREADS, 1)
void concept_mma_kernel(const float* __restrict__ q,
                        float* __restrict__ vec_out,
                        float* __restrict__ p_out) {
    extern __shared__ char smem[];
    const uint32_t sb = smem_u32(smem);
    const int tid  = threadIdx.x;
    const int lane = tid & 31;
    const int w    = tid >> 5;
    const int wm   = w >> 1, wn = w & 1;             // 2m x 2n warp grid
    const size_t b0 = (size_t)blockIdx.x * TMR;

    float* rinvs = (float*)(smem + OFF_RINV);        // ssq -> 1/||q||
    float* psum  = (float*)(smem + OFF_PSUM);        // row sums -> 1/sum

    if (tid < TMR) { rinvs[tid] = 0.f; psum[tid] = 0.f; }
    __syncthreads();

    // preload GEMM1 chunks 0,1 (DMA overlaps Q conversion below)
    load_b1_chunk(sb, OFF_B1A, 0, tid);
    load_b1_chunk(sb, OFF_B1B, 1, tid);

    // ---- Q: load f32, accumulate ssq, convert to fp16 SMEM tile ----
    #pragma unroll
    for (int i = 0; i < 32; i++) {
        int idx = i * 128 + tid;
        int row = idx >> 6, c4 = idx & 63;
        float4 v = *(const float4*)(q + (b0 + row) * D + c4 * 4);
        float ss = v.x * v.x + v.y * v.y + v.z * v.z + v.w * v.w;
        atomicAdd(&rinvs[row], ss);
        __half2 h0 = __floats2half2_rn(v.x, v.y);
        __half2 h1 = __floats2half2_rn(v.z, v.w);
        uint2 u = make_uint2(*(uint32_t*)&h0, *(uint32_t*)&h1);
        *(uint2*)(smem + OFF_QH + (row * QH_LDH + c4 * 4) * 2) = u;
    }
    __syncthreads();
    if (tid < TMR) rinvs[tid] = 1.0f / fmaxf(sqrtf(rinvs[tid]), 1e-12f);

    // ldmatrix lane->address mapping (A: x4 covers m16k16; B: x4 covers 2 n8-tiles' k16)
    const int g    = lane >> 3;
    const int arow = (g & 1) * 8 + (lane & 7);       // == lane & 15
    const int ak   = (g >> 1) * 8;
    const int brow = (g >> 1) * 8 + (lane & 7);
    const int bk   = (g & 1) * 8;

    const uint32_t aoff1_0 = sb + OFF_QH + ((wm * 32 + arow) * QH_LDH + ak) * 2;
    const uint32_t aoff1_1 = aoff1_0 + 16 * QH_LDH * 2;
    const uint32_t bbase1  = ((wn * 32 + brow) * B1_LDH + bk) * 2;

    float acc[2][4][4];
    float rs[2][2] = {{0.f, 0.f}, {0.f, 0.f}};

    // ---- Phase 1: GEMM1  sims[64 x 512] = Qh @ embn^T, 8 chunks of n64 ----
    #pragma unroll 1
    for (int nc = 0; nc < 8; nc++) {
        if (nc < 7) cpa_wait1(); else cpa_wait0();
        __syncthreads();
        const uint32_t buf = sb + ((nc & 1) ? OFF_B1B : OFF_B1A) + bbase1;

        #pragma unroll
        for (int mt = 0; mt < 2; mt++)
            #pragma unroll
            for (int nt = 0; nt < 4; nt++)
                #pragma unroll
                for (int k = 0; k < 4; k++) acc[mt][nt][k] = 0.f;

        uint32_t af[2][8], bf[2][8];
        ldsm4(af[0],     aoff1_0);
        ldsm4(af[0] + 4, aoff1_1);
        ldsm4(bf[0],     buf);
        ldsm4(bf[0] + 4, buf + 16 * B1_LDH * 2);
        #pragma unroll
        for (int ks = 0; ks < 16; ks++) {
            const int cur = ks & 1, nxt = cur ^ 1;
            if (ks < 15) {
                const uint32_t ko = (uint32_t)(ks + 1) * 32;
                ldsm4(af[nxt],     aoff1_0 + ko);
                ldsm4(af[nxt] + 4, aoff1_1 + ko);
                ldsm4(bf[nxt],     buf + ko);
                ldsm4(bf[nxt] + 4, buf + 16 * B1_LDH * 2 + ko);
            }
            #pragma unroll
            for (int mt = 0; mt < 2; mt++)
                #pragma unroll
                for (int nt = 0; nt < 4; nt++)
                    mma16816(acc[mt][nt], af[cur] + mt * 4,
                             bf[cur][(nt >> 1) * 4 + (nt & 1) * 2],
                             bf[cur][(nt >> 1) * 4 + (nt & 1) * 2 + 1]);
        }
        __syncthreads();                              // all warps done reading buf
        if (nc < 6) load_b1_chunk(sb, (nc & 1) ? OFF_B1B : OFF_B1A, nc + 2, tid);

        // epilogue: scale by 1/||q||, exp, fp16 store to Eh, accumulate row sums
        #pragma unroll
        for (int mt = 0; mt < 2; mt++) {
            #pragma unroll
            for (int h = 0; h < 2; h++) {
                const int r = wm * 32 + mt * 16 + (lane >> 2) + h * 8;
                const float rv = rinvs[r];
                #pragma unroll
                for (int nt = 0; nt < 4; nt++) {
                    float e0 = fast_exp(acc[mt][nt][2 * h]     * rv);
                    float e1 = fast_exp(acc[mt][nt][2 * h + 1] * rv);
                    rs[mt][h] += e0 + e1;
                    __half2 hh = __floats2half2_rn(e0, e1);
                    const int col = nc * 64 + wn * 32 + nt * 8 + (lane & 3) * 2;
                    *(uint32_t*)(smem + OFF_EH + (r * EH_LDH + col) * 2) = *(uint32_t*)&hh;
                }
            }
        }
    }

    // row-sum reduction: quad shuffles then smem atomics
    #pragma unroll
    for (int mt = 0; mt < 2; mt++)
        #pragma unroll
        for (int h = 0; h < 2; h++) {
            float v = rs[mt][h];
            v += __shfl_xor_sync(0xffffffffu, v, 1);
            v += __shfl_xor_sync(0xffffffffu, v, 2);
            if ((lane & 3) == 0)
                atomicAdd(&psum[wm * 32 + mt * 16 + (lane >> 2) + h * 8], v);
        }
    __syncthreads();
    if (tid < TMR) psum[tid] = 1.0f / psum[tid];      // pinv

    // preload GEMM2 chunks 0,1 (region reuse is safe: all GEMM1 reads done)
    load_b2_chunk(sb, OFF_B2A, 0, tid);
    load_b2_chunk(sb, OFF_B2B, 1, tid);
    __syncthreads();                                   // pinv + Eh visible

    // ---- p output: p = Eh * pinv (coalesced float2 stores; overlaps B2 DMA) ----
    #pragma unroll 4
    for (int i = 0; i < 128; i++) {
        int idx = i * 128 + tid;
        int row = idx >> 8, pr = idx & 255;
        uint32_t u = *(uint32_t*)(smem + OFF_EH + (row * EH_LDH + pr * 2) * 2);
        __half2 hh = *(__half2*)&u;
        float2 f = __half22float2(hh);
        float pv = psum[row];
        *(float2*)(p_out + (b0 + row) * NBANK + pr * 2) = make_float2(f.x * pv, f.y * pv);
    }

    // ---- Phase 2: GEMM2  vec[64 x 256] = Eh @ embT^T, 4 chunks of d64 ----
    const uint32_t aoff2_0 = sb + OFF_EH + ((wm * 32 + arow) * EH_LDH + ak) * 2;
    const uint32_t aoff2_1 = aoff2_0 + 16 * EH_LDH * 2;
    const uint32_t bbase2  = ((wn * 32 + brow) * B2_LDH + bk) * 2;

    #pragma unroll 1
    for (int dc = 0; dc < 4; dc++) {
        if (dc < 3) cpa_wait1(); else cpa_wait0();
        __syncthreads();
        const uint32_t buf = sb + ((dc & 1) ? OFF_B2B : OFF_B2A) + bbase2;

        #pragma unroll
        for (int mt = 0; mt < 2; mt++)
            #pragma unroll
            for (int nt = 0; nt < 4; nt++)
                #pragma unroll
                for (int k = 0; k < 4; k++) acc[mt][nt][k] = 0.f;

        uint32_t af[2][8], bf[2][8];
        ldsm4(af[0],     aoff2_0);
        ldsm4(af[0] + 4, aoff2_1);
        ldsm4(bf[0],     buf);
        ldsm4(bf[0] + 4, buf + 16 * B2_LDH * 2);
        #pragma unroll
        for (int ks = 0; ks < 32; ks++) {
            const int cur = ks & 1, nxt = cur ^ 1;
            if (ks < 31) {
                const uint32_t ko = (uint32_t)(ks + 1) * 32;
                ldsm4(af[nxt],     aoff2_0 + ko);
                ldsm4(af[nxt] + 4, aoff2_1 + ko);
                ldsm4(bf[nxt],     buf + ko);
                ldsm4(bf[nxt] + 4, buf + 16 * B2_LDH * 2 + ko);
            }
            #pragma unroll
            for (int mt = 0; mt < 2; mt++)
                #pragma unroll
                for (int nt = 0; nt < 4; nt++)
                    mma16816(acc[mt][nt], af[cur] + mt * 4,
                             bf[cur][(nt >> 1) * 4 + (nt & 1) * 2],
                             bf[cur][(nt >> 1) * 4 + (nt & 1) * 2 + 1]);
        }
        __syncthreads();
        if (dc < 2) load_b2_chunk(sb, (dc & 1) ? OFF_B2B : OFF_B2A, dc + 2, tid);

        // epilogue: vec = acc * pinv (8B-aligned float2 stores)
        #pragma unroll
        for (int mt = 0; mt < 2; mt++) {
            #pragma unroll
            for (int h = 0; h < 2; h++) {
                const int r = wm * 32 + mt * 16 + (lane >> 2) + h * 8;
                const float pv = psum[r];
                #pragma unroll
                for (int nt = 0; nt < 4; nt++) {
                    const int d = dc * 64 + wn * 32 + nt * 8 + (lane & 3) * 2;
                    *(float2*)(vec_out + (b0 + r) * D + d) =
                        make_float2(acc[mt][nt][2 * h] * pv, acc[mt][nt][2 * h + 1] * pv);
                }
            }
        }
    }
}

extern "C" void kernel_launch(void* const* d_in, const int* in_sizes, int n_in,
                              void* d_out, int out_size) {
    const float* q   = (const float*)d_in[0];   // (B, 256)
    const float* emb = (const float*)d_in[1];   // (512, 256)
    const int B = in_sizes[0] / D;

    float* vec_out = (float*)d_out;                     // (B, 256)
    float* p_out   = (float*)d_out + (size_t)B * D;     // (B, 512)

    cudaFuncSetAttribute(concept_mma_kernel,
                         cudaFuncAttributeMaxDynamicSharedMemorySize, SMEM_TOTAL);

    norm_emb_kernel<<<NBANK, D>>>(emb);
    transpose_emb_kernel<<<dim3(NBANK / 32, D / 32), dim3(32, 8)>>>(emb);
    concept_mma_kernel<<<B / TMR, THREADS, SMEM_TOTAL>>>(q, vec_out, p_out);
}

// round 9
// speedup vs baseline: 6.4539x; 3.7881x over previous
#include <cuda_runtime.h>
#include <cuda_fp16.h>
#include <cstdint>
#include <math.h>

#define D       256
#define NBANK   512
#define TMR     64          // rows (queries) per CTA
#define THREADS 256

// ---------------- device scratch (no allocation allowed) ----------------
__device__ __half g_embn_h[NBANK * D];   // l2-normalized bank fp16, [n][d] (K-major, GEMM1 B)
__device__ __half g_embT_h[D * NBANK];   // raw bank transposed fp16, [d][n] (K-major, GEMM2 B)

// ---------------- SMEM layout ----------------
// strides in halves; +8 halves pad (16B) keeps ldmatrix row-banks conflict-free
#define QH_LDH 264         // Q: 64 x 256 (+8)
#define B1_LDH 136         // B1 chunk: 128 n-rows x 128 k (+8)
#define EH_LDH 520         // Eh: 64 x 512 (+8)
#define B2_LDH 520         // B2 chunk: 64 d-rows x 512 k (+8)

#define OFF_EH   0
#define OFF_QH   (TMR * EH_LDH * 2)                    // 66560
#define OFF_B1A  (OFF_QH + TMR * QH_LDH * 2)           // 100352
#define OFF_B1B  (OFF_B1A + 128 * B1_LDH * 2)          // 135168
#define OFF_B2A  OFF_QH                                // phase 2 overlays QH/B1
#define OFF_B2B  (OFF_B2A + TMR * B2_LDH * 2)          // 133120
#define OFF_RINV (OFF_B2B + TMR * B2_LDH * 2)          // 199680
#define OFF_PSUM (OFF_RINV + 256)
#define SMEM_TOTAL (OFF_PSUM + 256)                    // 200192 bytes

// ---------------- asm helpers (sm_80-era only; no 'a'-suffix features) ----------------
__device__ __forceinline__ uint32_t smem_u32(const void* p) {
    uint32_t a;
    asm("{ .reg .u64 t; cvta.to.shared.u64 t, %1; cvt.u32.u64 %0, t; }" : "=r"(a) : "l"(p));
    return a;
}
__device__ __forceinline__ void ldsm4(uint32_t* r, uint32_t a) {
    asm volatile("ldmatrix.sync.aligned.m8n8.x4.shared.b16 {%0,%1,%2,%3}, [%4];"
        : "=r"(r[0]), "=r"(r[1]), "=r"(r[2]), "=r"(r[3]) : "r"(a));
}
__device__ __forceinline__ void mma16816(float* c, const uint32_t* a, uint32_t b0, uint32_t b1) {
    asm volatile("mma.sync.aligned.m16n8k16.row.col.f32.f16.f16.f32 "
        "{%0,%1,%2,%3}, {%4,%5,%6,%7}, {%8,%9}, {%0,%1,%2,%3};"
        : "+f"(c[0]), "+f"(c[1]), "+f"(c[2]), "+f"(c[3])
        : "r"(a[0]), "r"(a[1]), "r"(a[2]), "r"(a[3]), "r"(b0), "r"(b1));
}
__device__ __forceinline__ void cpa16(uint32_t s, const void* g) {
    asm volatile("cp.async.cg.shared.global [%0], [%1], 16;" :: "r"(s), "l"(g));
}
__device__ __forceinline__ void cpa_commit() { asm volatile("cp.async.commit_group;" ::: "memory"); }
__device__ __forceinline__ void cpa_wait1()  { asm volatile("cp.async.wait_group 1;" ::: "memory"); }
__device__ __forceinline__ void cpa_wait0()  { asm volatile("cp.async.wait_group 0;" ::: "memory"); }

// exp(x), x in [-1.05, 1.05], FMA-only (avoids chip-wide MUFU floor for 134M exps)
__device__ __forceinline__ float fast_exp(float x) {
    float t = x * 1.4426950408889634f;
    float r = t + 12582912.0f;
    int   i = __float_as_int(r) - 0x4B400000;
    float f = t - (r - 12582912.0f);
    float p = 1.5403530393381608e-4f;
    p = fmaf(p, f, 1.3333558146428443e-3f);
    p = fmaf(p, f, 9.6181291076284770e-3f);
    p = fmaf(p, f, 5.5504108664821580e-2f);
    p = fmaf(p, f, 2.4022650695910071e-1f);
    p = fmaf(p, f, 6.9314718055994531e-1f);
    p = fmaf(p, f, 1.0f);
    return __int_as_float(__float_as_int(p) + (i << 23));
}

// ---------------- merged prologue: normalize bank + transposed raw bank ----------------
__global__ void prep_emb_kernel(const float* __restrict__ emb) {
    int n = blockIdx.x, t = threadIdx.x;     // 512 blocks x 256 threads
    float e = emb[n * D + t];
    __shared__ float red[8];
    float s = e * e;
    #pragma unroll
    for (int o = 16; o > 0; o >>= 1) s += __shfl_xor_sync(0xffffffffu, s, o);
    if ((t & 31) == 0) red[t >> 5] = s;
    __syncthreads();
    if (t < 8) {
        float v = red[t];
        #pragma unroll
        for (int o = 4; o > 0; o >>= 1) v += __shfl_xor_sync(0x000000ffu, v, o);
        if (t == 0) red[0] = v;
    }
    __syncthreads();
    float inv = 1.0f / fmaxf(sqrtf(red[0]), 1e-12f);
    g_embn_h[n * D + t] = __float2half(e * inv);
    g_embT_h[(size_t)t * NBANK + n] = __float2half(e);
}

// ---------------- cp.async chunk loaders (one commit group each) ----------------
__device__ __forceinline__ void load_b1_chunk(uint32_t sb, int bufoff, int nc, int kc, int tid) {
    const __half* gp = g_embn_h + (size_t)nc * 128 * D + kc * 128;
    #pragma unroll
    for (int i = 0; i < 8; i++) {                       // 128 rows x 16 segs of 16B
        int idx = i * 256 + tid;
        int row = idx >> 4, seg = idx & 15;
        cpa16(sb + bufoff + row * (B1_LDH * 2) + seg * 16, gp + (size_t)row * D + seg * 8);
    }
    cpa_commit();
}
__device__ __forceinline__ void load_b2_chunk(uint32_t sb, int bufoff, int dc, int tid) {
    const __half* gp = g_embT_h + (size_t)dc * 64 * NBANK;
    #pragma unroll
    for (int i = 0; i < 16; i++) {                      // 64 rows x 64 segs of 16B
        int idx = i * 256 + tid;
        int row = idx >> 6, seg = idx & 63;
        cpa16(sb + bufoff + row * (B2_LDH * 2) + seg * 16, gp + (size_t)row * NBANK + seg * 8);
    }
    cpa_commit();
}

// ---------------- main fused kernel ----------------
__global__ __launch_bounds__(THREADS, 1)
void concept_mma_kernel(const float* __restrict__ q,
                        float* __restrict__ vec_out,
                        float* __restrict__ p_out) {
    extern __shared__ char smem[];
    const uint32_t sb = smem_u32(smem);
    const int tid  = threadIdx.x;
    const int lane = tid & 31;
    const int w    = tid >> 5;                   // 8 warps
    const int wm   = w >> 2, wn = w & 3;         // 2m x 4n warp grid
    const size_t b0 = (size_t)blockIdx.x * TMR;

    float* rinvs = (float*)(smem + OFF_RINV);
    float* psum  = (float*)(smem + OFF_PSUM);
    if (tid < TMR) psum[tid] = 0.f;

    // preload GEMM1 chunks 0,1 (overlaps Q conversion)
    load_b1_chunk(sb, OFF_B1A, 0, 0, tid);
    load_b1_chunk(sb, OFF_B1B, 0, 1, tid);

    // ---- Q: load f32 (4 threads per row), ssq via quad shuffle, fp16 to SMEM ----
    {
        const int qrow = tid >> 2, qq = tid & 3;
        const float* qr = q + (b0 + qrow) * D + qq * 64;
        float ss = 0.f;
        #pragma unroll
        for (int i = 0; i < 16; i++) {
            float4 v = *(const float4*)(qr + i * 4);
            ss = fmaf(v.x, v.x, ss); ss = fmaf(v.y, v.y, ss);
            ss = fmaf(v.z, v.z, ss); ss = fmaf(v.w, v.w, ss);
            __half2 h0 = __floats2half2_rn(v.x, v.y);
            __half2 h1 = __floats2half2_rn(v.z, v.w);
            uint2 u = make_uint2(*(uint32_t*)&h0, *(uint32_t*)&h1);
            *(uint2*)(smem + OFF_QH + (qrow * QH_LDH + qq * 64 + i * 4) * 2) = u;
        }
        ss += __shfl_xor_sync(0xffffffffu, ss, 1);
        ss += __shfl_xor_sync(0xffffffffu, ss, 2);
        if ((lane & 3) == 0) rinvs[qrow] = 1.0f / fmaxf(sqrtf(ss), 1e-12f);
    }

    // ldmatrix lane->address maps (A x4: m16k16; B x4: n16k16)
    const int g    = lane >> 3;
    const int arow = (g & 1) * 8 + (lane & 7);
    const int ak   = (g >> 1) * 8;
    const int brow = (g >> 1) * 8 + (lane & 7);
    const int bk   = (g & 1) * 8;

    float acc[2][4][4];
    float rs[2][2] = {{0.f, 0.f}, {0.f, 0.f}};

    // ---- Phase 1: GEMM1  sims[64x512] = Qh @ embn^T  (4 n128-chunks x 2 k128-splits) ----
    #pragma unroll 1
    for (int c = 0; c < 8; c++) {
        const int nc = c >> 1, kc = c & 1;
        if (c < 7) cpa_wait1(); else cpa_wait0();
        __syncthreads();

        if (kc == 0) {
            #pragma unroll
            for (int mt = 0; mt < 2; mt++)
                #pragma unroll
                for (int nt = 0; nt < 4; nt++)
                    #pragma unroll
                    for (int k = 0; k < 4; k++) acc[mt][nt][k] = 0.f;
        }

        const uint32_t abase = sb + OFF_QH + ((wm * 32 + arow) * QH_LDH + kc * 128 + ak) * 2;
        const uint32_t bbase = sb + ((c & 1) ? OFF_B1B : OFF_B1A)
                             + ((wn * 32 + brow) * B1_LDH + bk) * 2;

        uint32_t af[2][8], bf[2][8];
        ldsm4(af[0],     abase);
        ldsm4(af[0] + 4, abase + 16 * QH_LDH * 2);
        ldsm4(bf[0],     bbase);
        ldsm4(bf[0] + 4, bbase + 16 * B1_LDH * 2);
        #pragma unroll
        for (int ks = 0; ks < 8; ks++) {
            const int cur = ks & 1, nxt = cur ^ 1;
            if (ks < 7) {
                const uint32_t ko = (uint32_t)(ks + 1) * 32;
                ldsm4(af[nxt],     abase + ko);
                ldsm4(af[nxt] + 4, abase + 16 * QH_LDH * 2 + ko);
                ldsm4(bf[nxt],     bbase + ko);
                ldsm4(bf[nxt] + 4, bbase + 16 * B1_LDH * 2 + ko);
            }
            #pragma unroll
            for (int mt = 0; mt < 2; mt++)
                #pragma unroll
                for (int nt = 0; nt < 4; nt++)
                    mma16816(acc[mt][nt], af[cur] + mt * 4, bf[cur][nt * 2], bf[cur][nt * 2 + 1]);
        }
        __syncthreads();                           // buffer free before refill
        if (c + 2 < 8) load_b1_chunk(sb, (c & 1) ? OFF_B1B : OFF_B1A, (c + 2) >> 1, (c + 2) & 1, tid);

        if (kc == 1) {                             // epilogue overlaps next DMA
            #pragma unroll
            for (int mt = 0; mt < 2; mt++) {
                #pragma unroll
                for (int h = 0; h < 2; h++) {
                    const int r = wm * 32 + mt * 16 + (lane >> 2) + h * 8;
                    const float rv = rinvs[r];
                    #pragma unroll
                    for (int nt = 0; nt < 4; nt++) {
                        float e0 = fast_exp(acc[mt][nt][2 * h]     * rv);
                        float e1 = fast_exp(acc[mt][nt][2 * h + 1] * rv);
                        rs[mt][h] += e0 + e1;
                        __half2 hh = __floats2half2_rn(e0, e1);
                        const int col = nc * 128 + wn * 32 + nt * 8 + (lane & 3) * 2;
                        *(uint32_t*)(smem + OFF_EH + (r * EH_LDH + col) * 2) = *(uint32_t*)&hh;
                    }
                }
            }
        }
    }

    // ---- row sums -> pinv ----
    #pragma unroll
    for (int mt = 0; mt < 2; mt++)
        #pragma unroll
        for (int h = 0; h < 2; h++) {
            float v = rs[mt][h];
            v += __shfl_xor_sync(0xffffffffu, v, 1);
            v += __shfl_xor_sync(0xffffffffu, v, 2);
            if ((lane & 3) == 0)
                atomicAdd(&psum[wm * 32 + mt * 16 + (lane >> 2) + h * 8], v);
        }
    __syncthreads();
    if (tid < TMR) psum[tid] = 1.0f / psum[tid];
    __syncthreads();

    // preload GEMM2 chunks 0,1 (QH/B1 region now dead)
    load_b2_chunk(sb, OFF_B2A, 0, tid);
    load_b2_chunk(sb, OFF_B2B, 1, tid);

    // ---- p output (overlaps B2 DMA): p = Eh * pinv, float4 stores ----
    #pragma unroll 2
    for (int i = 0; i < 32; i++) {
        int idx = i * 256 + tid;
        int row = idx >> 7, pr = idx & 127;
        uint2 u = *(uint2*)(smem + OFF_EH + (row * EH_LDH + pr * 4) * 2);
        __half2 h0 = *(__half2*)&u.x, h1 = *(__half2*)&u.y;
        float2 f0 = __half22float2(h0), f1 = __half22float2(h1);
        float pv = psum[row];
        *(float4*)(p_out + (b0 + row) * NBANK + pr * 4) =
            make_float4(f0.x * pv, f0.y * pv, f1.x * pv, f1.y * pv);
    }

    // ---- Phase 2: GEMM2  vec[64x256] = Eh @ embT^T  (4 d64-chunks, k=512) ----
    float ac2[2][2][4];
    #pragma unroll 1
    for (int dc = 0; dc < 4; dc++) {
        if (dc < 3) cpa_wait1(); else cpa_wait0();
        __syncthreads();

        #pragma unroll
        for (int mt = 0; mt < 2; mt++)
            #pragma unroll
            for (int nt = 0; nt < 2; nt++)
                #pragma unroll
                for (int k = 0; k < 4; k++) ac2[mt][nt][k] = 0.f;

        const uint32_t abase = sb + OFF_EH + ((wm * 32 + arow) * EH_LDH + ak) * 2;
        const uint32_t bbase = sb + ((dc & 1) ? OFF_B2B : OFF_B2A)
                             + ((wn * 16 + brow) * B2_LDH + bk) * 2;

        uint32_t af[2][8], bf[2][4];
        ldsm4(af[0],     abase);
        ldsm4(af[0] + 4, abase + 16 * EH_LDH * 2);
        ldsm4(bf[0],     bbase);
        #pragma unroll
        for (int ks = 0; ks < 32; ks++) {
            const int cur = ks & 1, nxt = cur ^ 1;
            if (ks < 31) {
                const uint32_t ko = (uint32_t)(ks + 1) * 32;
                ldsm4(af[nxt],     abase + ko);
                ldsm4(af[nxt] + 4, abase + 16 * EH_LDH * 2 + ko);
                ldsm4(bf[nxt],     bbase + ko);
            }
            #pragma unroll
            for (int mt = 0; mt < 2; mt++)
                #pragma unroll
                for (int nt = 0; nt < 2; nt++)
                    mma16816(ac2[mt][nt], af[cur] + mt * 4, bf[cur][nt * 2], bf[cur][nt * 2 + 1]);
        }
        __syncthreads();
        if (dc + 2 < 4) load_b2_chunk(sb, (dc & 1) ? OFF_B2B : OFF_B2A, dc + 2, tid);

        // epilogue: vec = acc * pinv
        #pragma unroll
        for (int mt = 0; mt < 2; mt++) {
            #pragma unroll
            for (int h = 0; h < 2; h++) {
                const int r = wm * 32 + mt * 16 + (lane >> 2) + h * 8;
                const float pv = psum[r];
                #pragma unroll
                for (int nt = 0; nt < 2; nt++) {
                    const int d = dc * 64 + wn * 16 + nt * 8 + (lane & 3) * 2;
                    *(float2*)(vec_out + (b0 + r) * D + d) =
                        make_float2(ac2[mt][nt][2 * h] * pv, ac2[mt][nt][2 * h + 1] * pv);
                }
            }
        }
    }
}

extern "C" void kernel_launch(void* const* d_in, const int* in_sizes, int n_in,
                              void* d_out, int out_size) {
    const float* q   = (const float*)d_in[0];   // (B, 256)
    const float* emb = (const float*)d_in[1];   // (512, 256)
    const int B = in_sizes[0] / D;

    float* vec_out = (float*)d_out;                     // (B, 256)
    float* p_out   = (float*)d_out + (size_t)B * D;     // (B, 512)

    cudaFuncSetAttribute(concept_mma_kernel,
                         cudaFuncAttributeMaxDynamicSharedMemorySize, SMEM_TOTAL);

    prep_emb_kernel<<<NBANK, D>>>(emb);
    concept_mma_kernel<<<B / TMR, THREADS, SMEM_TOTAL>>>(q, vec_out, p_out);
}

// round 10
// speedup vs baseline: 6.9779x; 1.0812x over previous
#include <cuda_runtime.h>
#include <cuda_fp16.h>
#include <cstdint>
#include <math.h>

#define D       256
#define NBANK   512
#define TMR     64          // rows (queries) per CTA
#define THREADS 256

// ---------------- device scratch (no allocation allowed) ----------------
__device__ __half g_embn_h[NBANK * D];   // l2-normalized bank fp16, [n][d] (K-major, GEMM1 B)
__device__ __half g_embT_h[D * NBANK];   // raw bank transposed fp16, [d][n] (K-major, GEMM2 B)

// ---------------- SMEM layout (bytes), two overlaid phases ----------------
// all row strides are 16B-odd multiples (x mod 128B == 16) -> ldmatrix conflict-free
#define QH_LDH 264         // Q: 64 rows x 256 k (+8)
#define B1_LDH 72          // B1 chunk: 512 n-rows x 64 k (+8)
#define EH_LDH 520         // Eh: 64 rows x 512 k (+8)
#define B2_LDH 136         // B2 chunk: 256 d-rows x 128 k (+8)

#define OFF_QH   0                                   // phase1: Q          [0      , 33792)
#define OFF_B1A  33792                               // phase1: B1 buf A   [33792  , 107520)
#define OFF_B1B  107520                              // phase1: B1 buf B   [107520 , 181248)
#define OFF_EH   0                                   // phase2: Eh         [0      , 66560)
#define OFF_B2A  66560                               // phase2: B2 buf A   [66560  , 136192)
#define OFF_B2B  136192                              // phase2: B2 buf B   [136192 , 205824)
#define OFF_RINV 205824
#define OFF_PSUM (OFF_RINV + 256)
#define SMEM_TOTAL (OFF_PSUM + 256)                  // 206336 bytes

// ---------------- asm helpers (sm_80-era only; no 'a'-suffix features) ----------------
__device__ __forceinline__ uint32_t smem_u32(const void* p) {
    uint32_t a;
    asm("{ .reg .u64 t; cvta.to.shared.u64 t, %1; cvt.u32.u64 %0, t; }" : "=r"(a) : "l"(p));
    return a;
}
__device__ __forceinline__ void ldsm4(uint32_t* r, uint32_t a) {
    asm volatile("ldmatrix.sync.aligned.m8n8.x4.shared.b16 {%0,%1,%2,%3}, [%4];"
        : "=r"(r[0]), "=r"(r[1]), "=r"(r[2]), "=r"(r[3]) : "r"(a));
}
__device__ __forceinline__ void mma16816(float* c, const uint32_t* a, uint32_t b0, uint32_t b1) {
    asm volatile("mma.sync.aligned.m16n8k16.row.col.f32.f16.f16.f32 "
        "{%0,%1,%2,%3}, {%4,%5,%6,%7}, {%8,%9}, {%0,%1,%2,%3};"
        : "+f"(c[0]), "+f"(c[1]), "+f"(c[2]), "+f"(c[3])
        : "r"(a[0]), "r"(a[1]), "r"(a[2]), "r"(a[3]), "r"(b0), "r"(b1));
}
__device__ __forceinline__ void cpa16(uint32_t s, const void* g) {
    asm volatile("cp.async.cg.shared.global [%0], [%1], 16;" :: "r"(s), "l"(g));
}
__device__ __forceinline__ void cpa_commit() { asm volatile("cp.async.commit_group;" ::: "memory"); }
__device__ __forceinline__ void cpa_wait1()  { asm volatile("cp.async.wait_group 1;" ::: "memory"); }
__device__ __forceinline__ void cpa_wait0()  { asm volatile("cp.async.wait_group 0;" ::: "memory"); }

// exp(x), x in [-1.05, 1.05], FMA-only (avoids chip-wide MUFU floor for 134M exps)
__device__ __forceinline__ float fast_exp(float x) {
    float t = x * 1.4426950408889634f;
    float r = t + 12582912.0f;
    int   i = __float_as_int(r) - 0x4B400000;
    float f = t - (r - 12582912.0f);
    float p = 1.5403530393381608e-4f;
    p = fmaf(p, f, 1.3333558146428443e-3f);
    p = fmaf(p, f, 9.6181291076284770e-3f);
    p = fmaf(p, f, 5.5504108664821580e-2f);
    p = fmaf(p, f, 2.4022650695910071e-1f);
    p = fmaf(p, f, 6.9314718055994531e-1f);
    p = fmaf(p, f, 1.0f);
    return __int_as_float(__float_as_int(p) + (i << 23));
}

// ---------------- merged prologue: normalized bank + transposed raw bank ----------------
__global__ void prep_emb_kernel(const float* __restrict__ emb) {
    int n = blockIdx.x, t = threadIdx.x;     // 512 blocks x 256 threads
    float e = emb[n * D + t];
    __shared__ float red[8];
    float s = e * e;
    #pragma unroll
    for (int o = 16; o > 0; o >>= 1) s += __shfl_xor_sync(0xffffffffu, s, o);
    if ((t & 31) == 0) red[t >> 5] = s;
    __syncthreads();
    if (t < 8) {
        float v = red[t];
        #pragma unroll
        for (int o = 4; o > 0; o >>= 1) v += __shfl_xor_sync(0x000000ffu, v, o);
        if (t == 0) red[0] = v;
    }
    __syncthreads();
    float inv = 1.0f / fmaxf(sqrtf(red[0]), 1e-12f);
    g_embn_h[n * D + t] = __float2half(e * inv);
    g_embT_h[(size_t)t * NBANK + n] = __float2half(e);
}

// ---------------- cp.async chunk loaders (one commit group each) ----------------
// B1 chunk: n512 x k64 (GEMM1 B), k-offset kc*64
__device__ __forceinline__ void load_b1_chunk(uint32_t sb, int bufoff, int kc, int tid) {
    const __half* gp = g_embn_h + kc * 64;
    #pragma unroll
    for (int i = 0; i < 16; i++) {                      // 512 rows x 8 segs of 16B
        int idx = i * 256 + tid;
        int row = idx >> 3, seg = idx & 7;
        cpa16(sb + bufoff + row * (B1_LDH * 2) + seg * 16, gp + (size_t)row * D + seg * 8);
    }
    cpa_commit();
}
// B2 chunk: d256 x k128 (GEMM2 B), k-offset kc*128
__device__ __forceinline__ void load_b2_chunk(uint32_t sb, int bufoff, int kc, int tid) {
    const __half* gp = g_embT_h + kc * 128;
    #pragma unroll
    for (int i = 0; i < 16; i++) {                      // 256 rows x 16 segs of 16B
        int idx = i * 256 + tid;
        int row = idx >> 4, seg = idx & 15;
        cpa16(sb + bufoff + row * (B2_LDH * 2) + seg * 16, gp + (size_t)row * NBANK + seg * 8);
    }
    cpa_commit();
}

// ---------------- main fused kernel ----------------
__global__ __launch_bounds__(THREADS, 1)
void concept_mma_kernel(const float* __restrict__ q,
                        float* __restrict__ vec_out,
                        float* __restrict__ p_out) {
    extern __shared__ char smem[];
    const uint32_t sb = smem_u32(smem);
    const int tid  = threadIdx.x;
    const int lane = tid & 31;
    const int wn   = tid >> 5;                   // 8 warps, 1m x 8n grid
    const size_t b0 = (size_t)blockIdx.x * TMR;

    float* rinvs = (float*)(smem + OFF_RINV);
    float* psum  = (float*)(smem + OFF_PSUM);
    if (tid < TMR) psum[tid] = 0.f;

    // preload GEMM1 k-chunks 0,1 (overlaps Q conversion)
    load_b1_chunk(sb, OFF_B1A, 0, tid);
    load_b1_chunk(sb, OFF_B1B, 1, tid);

    // ---- Q: load f32 (4 threads/row), ssq via quad shuffle, fp16 to SMEM ----
    {
        const int qrow = tid >> 2, qq = tid & 3;
        const float* qr = q + (b0 + qrow) * D + qq * 64;
        float ss = 0.f;
        #pragma unroll
        for (int i = 0; i < 16; i++) {
            float4 v = *(const float4*)(qr + i * 4);
            ss = fmaf(v.x, v.x, ss); ss = fmaf(v.y, v.y, ss);
            ss = fmaf(v.z, v.z, ss); ss = fmaf(v.w, v.w, ss);
            __half2 h0 = __floats2half2_rn(v.x, v.y);
            __half2 h1 = __floats2half2_rn(v.z, v.w);
            uint2 u = make_uint2(*(uint32_t*)&h0, *(uint32_t*)&h1);
            *(uint2*)(smem + OFF_QH + (qrow * QH_LDH + qq * 64 + i * 4) * 2) = u;
        }
        ss += __shfl_xor_sync(0xffffffffu, ss, 1);
        ss += __shfl_xor_sync(0xffffffffu, ss, 2);
        if ((lane & 3) == 0) rinvs[qrow] = 1.0f / fmaxf(sqrtf(ss), 1e-12f);
    }

    // ldmatrix lane->address maps (proven in R9)
    const int g    = lane >> 3;
    const int arow = (g & 1) * 8 + (lane & 7);
    const int ak   = (g >> 1) * 8;
    const int brow = (g >> 1) * 8 + (lane & 7);
    const int bk   = (g & 1) * 8;

    // ---- Phase 1: GEMM1  sims[64x512] = Qh @ embn^T  (warp m64 x n64; 4 k64-chunks) ----
    float acc[4][8][4];
    #pragma unroll
    for (int mt = 0; mt < 4; mt++)
        #pragma unroll
        for (int nt = 0; nt < 8; nt++)
            #pragma unroll
            for (int k = 0; k < 4; k++) acc[mt][nt][k] = 0.f;

    #pragma unroll 1
    for (int kc = 0; kc < 4; kc++) {
        if (kc < 3) cpa_wait1(); else cpa_wait0();
        __syncthreads();                               // also publishes Q on kc==0
        const uint32_t buf   = sb + ((kc & 1) ? OFF_B1B : OFF_B1A);
        const uint32_t abase = sb + OFF_QH + ((arow)*QH_LDH + kc * 64 + ak) * 2;
        const uint32_t bbase = buf + ((wn * 64 + brow) * B1_LDH + bk) * 2;

        #pragma unroll
        for (int ks = 0; ks < 4; ks++) {
            const uint32_t ko = (uint32_t)ks * 32;
            uint32_t af[16], bf[16];
            ldsm4(af,      abase + ko);
            ldsm4(af + 4,  abase + 16 * QH_LDH * 2 + ko);
            ldsm4(af + 8,  abase + 32 * QH_LDH * 2 + ko);
            ldsm4(af + 12, abase + 48 * QH_LDH * 2 + ko);
            ldsm4(bf,      bbase + ko);
            ldsm4(bf + 4,  bbase + 16 * B1_LDH * 2 + ko);
            ldsm4(bf + 8,  bbase + 32 * B1_LDH * 2 + ko);
            ldsm4(bf + 12, bbase + 48 * B1_LDH * 2 + ko);
            #pragma unroll
            for (int mt = 0; mt < 4; mt++)
                #pragma unroll
                for (int nt = 0; nt < 8; nt++)
                    mma16816(acc[mt][nt], af + mt * 4, bf[nt * 2], bf[nt * 2 + 1]);
        }
        __syncthreads();                               // buffer free before refill
        if (kc + 2 < 4) load_b1_chunk(sb, (kc & 1) ? OFF_B1B : OFF_B1A, kc + 2, tid);
    }

    // ---- epilogue: exp in-place in acc, row sums, Eh store ----
    float rv[4][2];
    #pragma unroll
    for (int mt = 0; mt < 4; mt++)
        #pragma unroll
        for (int h = 0; h < 2; h++) rv[mt][h] = rinvs[mt * 16 + (lane >> 2) + h * 8];

    float rs[4][2] = {{0.f,0.f},{0.f,0.f},{0.f,0.f},{0.f,0.f}};
    #pragma unroll
    for (int mt = 0; mt < 4; mt++)
        #pragma unroll
        for (int nt = 0; nt < 8; nt++)
            #pragma unroll
            for (int h = 0; h < 2; h++) {
                float e0 = fast_exp(acc[mt][nt][2 * h]     * rv[mt][h]);
                float e1 = fast_exp(acc[mt][nt][2 * h + 1] * rv[mt][h]);
                rs[mt][h] += e0 + e1;
                acc[mt][nt][2 * h] = e0; acc[mt][nt][2 * h + 1] = e1;
            }
    #pragma unroll
    for (int mt = 0; mt < 4; mt++)
        #pragma unroll
        for (int h = 0; h < 2; h++) {
            float v = rs[mt][h];
            v += __shfl_xor_sync(0xffffffffu, v, 1);
            v += __shfl_xor_sync(0xffffffffu, v, 2);
            if ((lane & 3) == 0)
                atomicAdd(&psum[mt * 16 + (lane >> 2) + h * 8], v);
        }
    // Eh (fp16) for GEMM2 A operand; bank = 4*(lane>>2 mod 8)+t -> conflict-free
    #pragma unroll
    for (int mt = 0; mt < 4; mt++)
        #pragma unroll
        for (int h = 0; h < 2; h++) {
            const int r = mt * 16 + (lane >> 2) + h * 8;
            #pragma unroll
            for (int nt = 0; nt < 8; nt++) {
                __half2 hh = __floats2half2_rn(acc[mt][nt][2 * h], acc[mt][nt][2 * h + 1]);
                const int col = wn * 64 + nt * 8 + (lane & 3) * 2;
                *(uint32_t*)(smem + OFF_EH + (r * EH_LDH + col) * 2) = *(uint32_t*)&hh;
            }
        }
    __syncthreads();                                   // Eh + psum complete (B1 dead)

    load_b2_chunk(sb, OFF_B2A, 0, tid);                // overlaps pinv + p stores
    if (tid < TMR) psum[tid] = 1.0f / psum[tid];
    __syncthreads();

    // ---- p output directly from registers: p = e * pinv (float2, 32B sectors) ----
    #pragma unroll
    for (int mt = 0; mt < 4; mt++)
        #pragma unroll
        for (int h = 0; h < 2; h++) {
            const int r = mt * 16 + (lane >> 2) + h * 8;
            const float pv = psum[r];
            #pragma unroll
            for (int nt = 0; nt < 8; nt++) {
                const int col = wn * 64 + nt * 8 + (lane & 3) * 2;
                *(float2*)(p_out + (b0 + r) * NBANK + col) =
                    make_float2(acc[mt][nt][2 * h] * pv, acc[mt][nt][2 * h + 1] * pv);
            }
        }
    load_b2_chunk(sb, OFF_B2B, 1, tid);

    // ---- Phase 2: GEMM2  vec[64x256] = Eh @ embT^T  (warp m64 x d32; 4 k128-chunks) ----
    float ac2[4][4][4];
    #pragma unroll
    for (int mt = 0; mt < 4; mt++)
        #pragma unroll
        for (int nt = 0; nt < 4; nt++)
            #pragma unroll
            for (int k = 0; k < 4; k++) ac2[mt][nt][k] = 0.f;

    #pragma unroll 1
    for (int kc = 0; kc < 4; kc++) {
        if (kc < 3) cpa_wait1(); else cpa_wait0();
        __syncthreads();
        const uint32_t buf   = sb + ((kc & 1) ? OFF_B2B : OFF_B2A);
        const uint32_t abase = sb + OFF_EH + ((arow)*EH_LDH + kc * 128 + ak) * 2;
        const uint32_t bbase = buf + ((wn * 32 + brow) * B2_LDH + bk) * 2;

        #pragma unroll
        for (int ks = 0; ks < 8; ks++) {
            const uint32_t ko = (uint32_t)ks * 32;
            uint32_t af[16], bf[8];
            ldsm4(af,      abase + ko);
            ldsm4(af + 4,  abase + 16 * EH_LDH * 2 + ko);
            ldsm4(af + 8,  abase + 32 * EH_LDH * 2 + ko);
            ldsm4(af + 12, abase + 48 * EH_LDH * 2 + ko);
            ldsm4(bf,      bbase + ko);
            ldsm4(bf + 4,  bbase + 16 * B2_LDH * 2 + ko);
            #pragma unroll
            for (int mt = 0; mt < 4; mt++)
                #pragma unroll
                for (int nt = 0; nt < 4; nt++)
                    mma16816(ac2[mt][nt], af + mt * 4, bf[nt * 2], bf[nt * 2 + 1]);
        }
        __syncthreads();
        if (kc + 2 < 4) load_b2_chunk(sb, (kc & 1) ? OFF_B2B : OFF_B2A, kc + 2, tid);
    }

    // ---- vec epilogue: vec = acc2 * pinv ----
    #pragma unroll
    for (int mt = 0; mt < 4; mt++)
        #pragma unroll
        for (int h = 0; h < 2; h++) {
            const int r = mt * 16 + (lane >> 2) + h * 8;
            const float pv = psum[r];
            #pragma unroll
            for (int nt = 0; nt < 4; nt++) {
                const int d = wn * 32 + nt * 8 + (lane & 3) * 2;
                *(float2*)(vec_out + (b0 + r) * D + d) =
                    make_float2(ac2[mt][nt][2 * h] * pv, ac2[mt][nt][2 * h + 1] * pv);
            }
        }
}

extern "C" void kernel_launch(void* const* d_in, const int* in_sizes, int n_in,
                              void* d_out, int out_size) {
    const float* q   = (const float*)d_in[0];   // (B, 256)
    const float* emb = (const float*)d_in[1];   // (512, 256)
    const int B = in_sizes[0] / D;

    float* vec_out = (float*)d_out;                     // (B, 256)
    float* p_out   = (float*)d_out + (size_t)B * D;     // (B, 512)

    cudaFuncSetAttribute(concept_mma_kernel,
                         cudaFuncAttributeMaxDynamicSharedMemorySize, SMEM_TOTAL);

    prep_emb_kernel<<<NBANK, D>>>(emb);
    concept_mma_kernel<<<B / TMR, THREADS, SMEM_TOTAL>>>(q, vec_out, p_out);
}

// round 11
// speedup vs baseline: 7.0820x; 1.0149x over previous
#include <cuda_runtime.h>
#include <cuda_fp16.h>
#include <cstdint>
#include <math.h>

#define D       256
#define NBANK   512
#define TMR     64          // rows (queries) per CTA
#define THREADS 512

// ---------------- device scratch (no allocation allowed) ----------------
__device__ __half g_embn_h[NBANK * D];   // l2-normalized bank fp16, [n][d] (K-major, GEMM1 B)
__device__ __half g_embT_h[D * NBANK];   // raw bank transposed fp16, [d][n] (K-major, GEMM2 B)

// ---------------- SMEM layout (bytes), two overlaid phases ----------------
// all row strides are 16B-odd multiples (x mod 128B == 16) -> ldmatrix conflict-free
#define QH_LDH 264         // Q: 64 rows x 256 k (+8)
#define B1_LDH 72          // B1 chunk: 512 n-rows x 64 k (+8)
#define EH_LDH 520         // Eh: 64 rows x 512 k (+8)
#define B2_LDH 136         // B2 chunk: 256 d-rows x 128 k (+8)

#define OFF_QH   0                                   // phase1: Q          [0      , 33792)
#define OFF_B1A  33792                               // phase1: B1 buf A   [33792  , 107520)
#define OFF_B1B  107520                              // phase1: B1 buf B   [107520 , 181248)
#define OFF_EH   0                                   // phase2: Eh         [0      , 66560)
#define OFF_B2A  66560                               // phase2: B2 buf A   [66560  , 136192)
#define OFF_B2B  136192                              // phase2: B2 buf B   [136192 , 205824)
#define OFF_RINV 205824
#define OFF_PSUM (OFF_RINV + 256)
#define SMEM_TOTAL (OFF_PSUM + 256)                  // 206336 bytes

// ---------------- asm helpers (sm_80-era only; no 'a'-suffix features) ----------------
__device__ __forceinline__ uint32_t smem_u32(const void* p) {
    uint32_t a;
    asm("{ .reg .u64 t; cvta.to.shared.u64 t, %1; cvt.u32.u64 %0, t; }" : "=r"(a) : "l"(p));
    return a;
}
__device__ __forceinline__ void ldsm4(uint32_t* r, uint32_t a) {
    asm volatile("ldmatrix.sync.aligned.m8n8.x4.shared.b16 {%0,%1,%2,%3}, [%4];"
        : "=r"(r[0]), "=r"(r[1]), "=r"(r[2]), "=r"(r[3]) : "r"(a));
}
__device__ __forceinline__ void mma16816(float* c, const uint32_t* a, uint32_t b0, uint32_t b1) {
    asm volatile("mma.sync.aligned.m16n8k16.row.col.f32.f16.f16.f32 "
        "{%0,%1,%2,%3}, {%4,%5,%6,%7}, {%8,%9}, {%0,%1,%2,%3};"
        : "+f"(c[0]), "+f"(c[1]), "+f"(c[2]), "+f"(c[3])
        : "r"(a[0]), "r"(a[1]), "r"(a[2]), "r"(a[3]), "r"(b0), "r"(b1));
}
__device__ __forceinline__ void cpa16(uint32_t s, const void* g) {
    asm volatile("cp.async.cg.shared.global [%0], [%1], 16;" :: "r"(s), "l"(g));
}
__device__ __forceinline__ void cpa_commit() { asm volatile("cp.async.commit_group;" ::: "memory"); }
__device__ __forceinline__ void cpa_wait1()  { asm volatile("cp.async.wait_group 1;" ::: "memory"); }
__device__ __forceinline__ void cpa_wait0()  { asm volatile("cp.async.wait_group 0;" ::: "memory"); }

// exp(x), x in [-1.05, 1.05], FMA-only (avoids chip-wide MUFU floor for 134M exps)
__device__ __forceinline__ float fast_exp(float x) {
    float t = x * 1.4426950408889634f;
    float r = t + 12582912.0f;
    int   i = __float_as_int(r) - 0x4B400000;
    float f = t - (r - 12582912.0f);
    float p = 1.5403530393381608e-4f;
    p = fmaf(p, f, 1.3333558146428443e-3f);
    p = fmaf(p, f, 9.6181291076284770e-3f);
    p = fmaf(p, f, 5.5504108664821580e-2f);
    p = fmaf(p, f, 2.4022650695910071e-1f);
    p = fmaf(p, f, 6.9314718055994531e-1f);
    p = fmaf(p, f, 1.0f);
    return __int_as_float(__float_as_int(p) + (i << 23));
}

// ---------------- merged prologue: normalized bank + transposed raw bank ----------------
__global__ void prep_emb_kernel(const float* __restrict__ emb) {
    int n = blockIdx.x, t = threadIdx.x;     // 512 blocks x 256 threads
    float e = emb[n * D + t];
    __shared__ float red[8];
    float s = e * e;
    #pragma unroll
    for (int o = 16; o > 0; o >>= 1) s += __shfl_xor_sync(0xffffffffu, s, o);
    if ((t & 31) == 0) red[t >> 5] = s;
    __syncthreads();
    if (t < 8) {
        float v = red[t];
        #pragma unroll
        for (int o = 4; o > 0; o >>= 1) v += __shfl_xor_sync(0x000000ffu, v, o);
        if (t == 0) red[0] = v;
    }
    __syncthreads();
    float inv = 1.0f / fmaxf(sqrtf(red[0]), 1e-12f);
    g_embn_h[n * D + t] = __float2half(e * inv);
    g_embT_h[(size_t)t * NBANK + n] = __float2half(e);
}

// ---------------- cp.async chunk loaders (512 threads, one commit group each) ----------------
// B1 chunk: n512 x k64 (GEMM1 B), k-offset kc*64
__device__ __forceinline__ void load_b1_chunk(uint32_t sb, int bufoff, int kc, int tid) {
    const __half* gp = g_embn_h + kc * 64;
    #pragma unroll
    for (int i = 0; i < 8; i++) {                       // 512 rows x 8 segs of 16B
        int idx = i * 512 + tid;
        int row = idx >> 3, seg = idx & 7;
        cpa16(sb + bufoff + row * (B1_LDH * 2) + seg * 16, gp + (size_t)row * D + seg * 8);
    }
    cpa_commit();
}
// B2 chunk: d256 x k128 (GEMM2 B), k-offset kc*128
__device__ __forceinline__ void load_b2_chunk(uint32_t sb, int bufoff, int kc, int tid) {
    const __half* gp = g_embT_h + kc * 128;
    #pragma unroll
    for (int i = 0; i < 8; i++) {                       // 256 rows x 16 segs of 16B
        int idx = i * 512 + tid;
        int row = idx >> 4, seg = idx & 15;
        cpa16(sb + bufoff + row * (B2_LDH * 2) + seg * 16, gp + (size_t)row * NBANK + seg * 8);
    }
    cpa_commit();
}

// ---------------- main fused kernel: 16 warps, 2m x 8n warp grid ----------------
__global__ __launch_bounds__(THREADS, 1)
void concept_mma_kernel(const float* __restrict__ q,
                        float* __restrict__ vec_out,
                        float* __restrict__ p_out) {
    extern __shared__ char smem[];
    const uint32_t sb = smem_u32(smem);
    const int tid  = threadIdx.x;
    const int lane = tid & 31;
    const int w    = tid >> 5;                   // 16 warps
    const int wm   = w >> 3, wn = w & 7;         // 2m x 8n grid (m32 x n64 / d32 tiles)
    const size_t b0 = (size_t)blockIdx.x * TMR;

    float* rinvs = (float*)(smem + OFF_RINV);
    float* psum  = (float*)(smem + OFF_PSUM);
    if (tid < TMR) psum[tid] = 0.f;

    // preload GEMM1 k-chunks 0,1 (overlaps Q conversion)
    load_b1_chunk(sb, OFF_B1A, 0, tid);
    load_b1_chunk(sb, OFF_B1B, 1, tid);

    // ---- Q: load f32 (8 threads/row), ssq via shuffle, fp16 to SMEM ----
    {
        const int qrow = tid >> 3, qq = tid & 7;     // 8 threads per row, 32 floats each
        const float* qr = q + (b0 + qrow) * D + qq * 32;
        float ss = 0.f;
        #pragma unroll
        for (int i = 0; i < 8; i++) {
            float4 v = *(const float4*)(qr + i * 4);
            ss = fmaf(v.x, v.x, ss); ss = fmaf(v.y, v.y, ss);
            ss = fmaf(v.z, v.z, ss); ss = fmaf(v.w, v.w, ss);
            __half2 h0 = __floats2half2_rn(v.x, v.y);
            __half2 h1 = __floats2half2_rn(v.z, v.w);
            uint2 u = make_uint2(*(uint32_t*)&h0, *(uint32_t*)&h1);
            *(uint2*)(smem + OFF_QH + (qrow * QH_LDH + qq * 32 + i * 4) * 2) = u;
        }
        ss += __shfl_xor_sync(0xffffffffu, ss, 1);
        ss += __shfl_xor_sync(0xffffffffu, ss, 2);
        ss += __shfl_xor_sync(0xffffffffu, ss, 4);
        if ((lane & 7) == 0) rinvs[qrow] = 1.0f / fmaxf(sqrtf(ss), 1e-12f);
    }

    // ldmatrix lane->address maps (proven in R9/R10)
    const int g    = lane >> 3;
    const int arow = (g & 1) * 8 + (lane & 7);
    const int ak   = (g >> 1) * 8;
    const int brow = (g >> 1) * 8 + (lane & 7);
    const int bk   = (g & 1) * 8;

    // ---- Phase 1: GEMM1  sims[64x512] = Qh @ embn^T  (warp m32 x n64; 4 k64-chunks) ----
    float acc[2][8][4];
    #pragma unroll
    for (int mt = 0; mt < 2; mt++)
        #pragma unroll
        for (int nt = 0; nt < 8; nt++)
            #pragma unroll
            for (int k = 0; k < 4; k++) acc[mt][nt][k] = 0.f;

    #pragma unroll 1
    for (int kc = 0; kc < 4; kc++) {
        if (kc < 3) cpa_wait1(); else cpa_wait0();
        __syncthreads();                               // also publishes Q on kc==0
        const uint32_t buf   = sb + ((kc & 1) ? OFF_B1B : OFF_B1A);
        const uint32_t abase = sb + OFF_QH + ((wm * 32 + arow) * QH_LDH + kc * 64 + ak) * 2;
        const uint32_t bbase = buf + ((wn * 64 + brow) * B1_LDH + bk) * 2;

        #pragma unroll
        for (int ks = 0; ks < 4; ks++) {
            const uint32_t ko = (uint32_t)ks * 32;
            uint32_t af[8], bf[16];
            ldsm4(af,      abase + ko);
            ldsm4(af + 4,  abase + 16 * QH_LDH * 2 + ko);
            ldsm4(bf,      bbase + ko);
            ldsm4(bf + 4,  bbase + 16 * B1_LDH * 2 + ko);
            ldsm4(bf + 8,  bbase + 32 * B1_LDH * 2 + ko);
            ldsm4(bf + 12, bbase + 48 * B1_LDH * 2 + ko);
            #pragma unroll
            for (int mt = 0; mt < 2; mt++)
                #pragma unroll
                for (int nt = 0; nt < 8; nt++)
                    mma16816(acc[mt][nt], af + mt * 4, bf[nt * 2], bf[nt * 2 + 1]);
        }
        __syncthreads();                               // buffer free before refill
        if (kc + 2 < 4) load_b1_chunk(sb, (kc & 1) ? OFF_B1B : OFF_B1A, kc + 2, tid);
    }

    // ---- epilogue: exp in-place in acc, row sums, Eh store ----
    float rv[2][2];
    #pragma unroll
    for (int mt = 0; mt < 2; mt++)
        #pragma unroll
        for (int h = 0; h < 2; h++)
            rv[mt][h] = rinvs[wm * 32 + mt * 16 + (lane >> 2) + h * 8];

    float rs[2][2] = {{0.f, 0.f}, {0.f, 0.f}};
    #pragma unroll
    for (int mt = 0; mt < 2; mt++)
        #pragma unroll
        for (int nt = 0; nt < 8; nt++)
            #pragma unroll
            for (int h = 0; h < 2; h++) {
                float e0 = fast_exp(acc[mt][nt][2 * h]     * rv[mt][h]);
                float e1 = fast_exp(acc[mt][nt][2 * h + 1] * rv[mt][h]);
                rs[mt][h] += e0 + e1;
                acc[mt][nt][2 * h] = e0; acc[mt][nt][2 * h + 1] = e1;
            }
    #pragma unroll
    for (int mt = 0; mt < 2; mt++)
        #pragma unroll
        for (int h = 0; h < 2; h++) {
            float v = rs[mt][h];
            v += __shfl_xor_sync(0xffffffffu, v, 1);
            v += __shfl_xor_sync(0xffffffffu, v, 2);
            if ((lane & 3) == 0)
                atomicAdd(&psum[wm * 32 + mt * 16 + (lane >> 2) + h * 8], v);
        }
    // Eh (fp16) for GEMM2 A operand
    #pragma unroll
    for (int mt = 0; mt < 2; mt++)
        #pragma unroll
        for (int h = 0; h < 2; h++) {
            const int r = wm * 32 + mt * 16 + (lane >> 2) + h * 8;
            #pragma unroll
            for (int nt = 0; nt < 8; nt++) {
                __half2 hh = __floats2half2_rn(acc[mt][nt][2 * h], acc[mt][nt][2 * h + 1]);
                const int col = wn * 64 + nt * 8 + (lane & 3) * 2;
                *(uint32_t*)(smem + OFF_EH + (r * EH_LDH + col) * 2) = *(uint32_t*)&hh;
            }
        }
    __syncthreads();                                   // Eh + psum complete (B1 dead)

    load_b2_chunk(sb, OFF_B2A, 0, tid);                // overlaps pinv + p stores
    if (tid < TMR) psum[tid] = 1.0f / psum[tid];
    __syncthreads();

    // ---- p output directly from registers: p = e * pinv (float2, 32B sectors) ----
    #pragma unroll
    for (int mt = 0; mt < 2; mt++)
        #pragma unroll
        for (int h = 0; h < 2; h++) {
            const int r = wm * 32 + mt * 16 + (lane >> 2) + h * 8;
            const float pv = psum[r];
            #pragma unroll
            for (int nt = 0; nt < 8; nt++) {
                const int col = wn * 64 + nt * 8 + (lane & 3) * 2;
                *(float2*)(p_out + (b0 + r) * NBANK + col) =
                    make_float2(acc[mt][nt][2 * h] * pv, acc[mt][nt][2 * h + 1] * pv);
            }
        }
    load_b2_chunk(sb, OFF_B2B, 1, tid);

    // ---- Phase 2: GEMM2  vec[64x256] = Eh @ embT^T  (warp m32 x d32; 4 k128-chunks) ----
    float ac2[2][4][4];
    #pragma unroll
    for (int mt = 0; mt < 2; mt++)
        #pragma unroll
        for (int nt = 0; nt < 4; nt++)
            #pragma unroll
            for (int k = 0; k < 4; k++) ac2[mt][nt][k] = 0.f;

    #pragma unroll 1
    for (int kc = 0; kc < 4; kc++) {
        if (kc < 3) cpa_wait1(); else cpa_wait0();
        __syncthreads();
        const uint32_t buf   = sb + ((kc & 1) ? OFF_B2B : OFF_B2A);
        const uint32_t abase = sb + OFF_EH + ((wm * 32 + arow) * EH_LDH + kc * 128 + ak) * 2;
        const uint32_t bbase = buf + ((wn * 32 + brow) * B2_LDH + bk) * 2;

        #pragma unroll
        for (int ks = 0; ks < 8; ks++) {
            const uint32_t ko = (uint32_t)ks * 32;
            uint32_t af[8], bf[8];
            ldsm4(af,     abase + ko);
            ldsm4(af + 4, abase + 16 * EH_LDH * 2 + ko);
            ldsm4(bf,     bbase + ko);
            ldsm4(bf + 4, bbase + 16 * B2_LDH * 2 + ko);
            #pragma unroll
            for (int mt = 0; mt < 2; mt++)
                #pragma unroll
                for (int nt = 0; nt < 4; nt++)
                    mma16816(ac2[mt][nt], af + mt * 4, bf[nt * 2], bf[nt * 2 + 1]);
        }
        __syncthreads();
        if (kc + 2 < 4) load_b2_chunk(sb, (kc & 1) ? OFF_B2B : OFF_B2A, kc + 2, tid);
    }

    // ---- vec epilogue: vec = acc2 * pinv ----
    #pragma unroll
    for (int mt = 0; mt < 2; mt++)
        #pragma unroll
        for (int h = 0; h < 2; h++) {
            const int r = wm * 32 + mt * 16 + (lane >> 2) + h * 8;
            const float pv = psum[r];
            #pragma unroll
            for (int nt = 0; nt < 4; nt++) {
                const int d = wn * 32 + nt * 8 + (lane & 3) * 2;
                *(float2*)(vec_out + (b0 + r) * D + d) =
                    make_float2(ac2[mt][nt][2 * h] * pv, ac2[mt][nt][2 * h + 1] * pv);
            }
        }
}

extern "C" void kernel_launch(void* const* d_in, const int* in_sizes, int n_in,
                              void* d_out, int out_size) {
    const float* q   = (const float*)d_in[0];   // (B, 256)
    const float* emb = (const float*)d_in[1];   // (512, 256)
    const int B = in_sizes[0] / D;

    float* vec_out = (float*)d_out;                     // (B, 256)
    float* p_out   = (float*)d_out + (size_t)B * D;     // (B, 512)

    cudaFuncSetAttribute(concept_mma_kernel,
                         cudaFuncAttributeMaxDynamicSharedMemorySize, SMEM_TOTAL);

    prep_emb_kernel<<<NBANK, D>>>(emb);
    concept_mma_kernel<<<B / TMR, THREADS, SMEM_TOTAL>>>(q, vec_out, p_out);
}